// round 15
// baseline (speedup 1.0000x reference)
#include <cuda_runtime.h>
#include <cuda_fp16.h>
#include <cstdint>
#include <math_constants.h>

#define B_DIM 4
#define T_DIM 4096
#define C_DIM 512
#define NEL   (B_DIM * T_DIM * C_DIM)
// scale * log2(e): Q is pre-multiplied so softmax uses exp2 directly
#define SCALE_L2E (0.044194173824159216f * 1.4426950408889634f)

// Scratch
__device__ __half g_Xh [3 * NEL];                 // fp16 inputs (q,k,v)
__device__ __half g_Wth[3 * C_DIM * C_DIM];       // fp16 W^T [n][k]
__device__ __half g_Qh [NEL];                     // Q proj * scale*log2e
__device__ __half g_Kh [NEL];
__device__ float  g_Vp [NEL];                     // V proj fp32
__device__ __half g_Vth[NEL];                     // V transposed [b][d][t]

__device__ __forceinline__ void cp16(void* s, const void* g) {
    uint32_t sa = (uint32_t)__cvta_generic_to_shared(s);
    asm volatile("cp.async.cg.shared.global [%0], [%1], 16;" :: "r"(sa), "l"(g));
}
#define CP_COMMIT asm volatile("cp.async.commit_group;")
#define CP_WAIT(N) asm volatile("cp.async.wait_group %0;" :: "n"(N))

#define MMA_F16(d, a0, a1, a2, a3, b0, b1)                                   \
    asm volatile(                                                            \
        "mma.sync.aligned.m16n8k16.row.col.f32.f16.f16.f32 "                 \
        "{%0,%1,%2,%3},{%4,%5,%6,%7},{%8,%9},{%0,%1,%2,%3};"                 \
        : "+f"((d)[0]), "+f"((d)[1]), "+f"((d)[2]), "+f"((d)[3])             \
        : "r"(a0), "r"(a1), "r"(a2), "r"(a3), "r"(b0), "r"(b1))

#define LDSM_X4(r0, r1, r2, r3, addr)                                        \
    asm volatile("ldmatrix.sync.aligned.m8n8.x4.shared.b16 {%0,%1,%2,%3}, [%4];" \
        : "=r"(r0), "=r"(r1), "=r"(r2), "=r"(r3) : "r"(addr))

// ============================================================================
// xconv: fp32 -> fp16 elementwise, 3 tensors. 8 floats/thread.
// ============================================================================
__global__ __launch_bounds__(256) void xconv_kernel(
    const float* __restrict__ xq, const float* __restrict__ xk, const float* __restrict__ xv)
{
    const int which = blockIdx.z;
    const float* src = (which == 0) ? xq : (which == 1) ? xk : xv;
    __half* dst = g_Xh + (size_t)which * NEL;
    size_t i = ((size_t)blockIdx.x * 256 + threadIdx.x) * 8;
    float4 f0 = *(const float4*)(src + i);
    float4 f1 = *(const float4*)(src + i + 4);
    __half2 h0 = __floats2half2_rn(f0.x, f0.y);
    __half2 h1 = __floats2half2_rn(f0.z, f0.w);
    __half2 h2 = __floats2half2_rn(f1.x, f1.y);
    __half2 h3 = __floats2half2_rn(f1.z, f1.w);
    uint4 u;
    u.x = *(uint32_t*)&h0; u.y = *(uint32_t*)&h1;
    u.z = *(uint32_t*)&h2; u.w = *(uint32_t*)&h3;
    *(uint4*)(dst + i) = u;
}

// ============================================================================
// wtrans: W [k][n] fp32 -> W^T [n][k] fp16. 32x32 tiles.
// ============================================================================
__global__ __launch_bounds__(256) void wtrans_kernel(
    const float* __restrict__ Wq, const float* __restrict__ Wk, const float* __restrict__ Wv)
{
    __shared__ float tile[32][33];
    const int which = blockIdx.z;
    const float* W = (which == 0) ? Wq : (which == 1) ? Wk : Wv;
    __half* Wt = g_Wth + (size_t)which * C_DIM * C_DIM;
    const int k0 = blockIdx.x * 32, n0 = blockIdx.y * 32;
    const int tx = threadIdx.x & 31, ty = threadIdx.x >> 5;
#pragma unroll
    for (int r = ty; r < 32; r += 8) tile[r][tx] = W[(size_t)(k0 + r) * C_DIM + n0 + tx];
    __syncthreads();
#pragma unroll
    for (int r = ty; r < 32; r += 8)
        Wt[(size_t)(n0 + r) * C_DIM + k0 + tx] = __float2half_rn(tile[tx][r]);
}

// ============================================================================
// proj: y = x @ W + b via fp16 m16n8k16 + ldmatrix. BM=128, BN=64, BK=64.
// 256 threads (4m x 2n warps). which 0: g_Qh (*scale*log2e); 1: g_Kh; 2: g_Vp f32.
// ============================================================================
#define PJ_A(buf)  ((buf) * 18432)            // 128 rows x 144B
#define PJ_B(buf)  (36864 + (buf) * 9216)     // 64 rows x 144B
#define PJ_SMEM    55296
#define PJ_ROWB    144

__global__ __launch_bounds__(256, 1) void proj_kernel(
    const float* __restrict__ bq, const float* __restrict__ bk, const float* __restrict__ bv)
{
    extern __shared__ char sm[];
    const int which = blockIdx.z;
    const __half* xh = g_Xh + (size_t)which * NEL;
    const __half* wt = g_Wth + (size_t)which * C_DIM * C_DIM;
    const float* bias = (which == 0) ? bq : (which == 1) ? bk : bv;

    const int m0 = blockIdx.x * 128;
    const int n0 = blockIdx.y * 64;
    const int tid = threadIdx.x, lane = tid & 31, wid = tid >> 5;
    const int wr = wid >> 1, wc = wid & 1;
    const int g = lane >> 2, t = lane & 3;

    const uint32_t smb = (uint32_t)__cvta_generic_to_shared(sm);
    const int arow = (lane & 15), akh = (lane >> 4) * 8;
    const int brow = ((lane >> 4) << 3) + (lane & 7), bkh = ((lane >> 3) & 1) * 8;

    float acc[2][4][4];
#pragma unroll
    for (int mt = 0; mt < 2; mt++)
#pragma unroll
        for (int nt = 0; nt < 4; nt++)
#pragma unroll
            for (int e = 0; e < 4; e++) acc[mt][nt][e] = 0.f;

    auto issue = [&](int buf, int kt) {
#pragma unroll
        for (int r = 0; r < 4; r++) {             // A: 128 x 64 halves
            int i = tid + 256 * r;
            int row = i >> 3, cf = i & 7;
            cp16(sm + PJ_A(buf) + row * PJ_ROWB + cf * 16,
                 xh + (size_t)(m0 + row) * C_DIM + kt * 64 + cf * 8);
        }
#pragma unroll
        for (int r = 0; r < 2; r++) {             // B: 64 x 64 halves
            int i = tid + 256 * r;
            int row = i >> 3, cf = i & 7;
            cp16(sm + PJ_B(buf) + row * PJ_ROWB + cf * 16,
                 wt + (size_t)(n0 + row) * C_DIM + kt * 64 + cf * 8);
        }
        CP_COMMIT;
    };

    issue(0, 0);
    for (int kt = 0; kt < 8; ++kt) {
        if (kt + 1 < 8) { issue((kt + 1) & 1, kt + 1); CP_WAIT(1); }
        else            { CP_WAIT(0); }
        __syncthreads();
        const int buf = kt & 1;
        const uint32_t aA0 = smb + PJ_A(buf) + (wr * 32 + arow) * PJ_ROWB + akh * 2;
        const uint32_t aA1 = aA0 + 16 * PJ_ROWB;
        const uint32_t bB0 = smb + PJ_B(buf) + (wc * 32 + brow) * PJ_ROWB + bkh * 2;
        const uint32_t bB1 = bB0 + 16 * PJ_ROWB;
#pragma unroll
        for (int kf = 0; kf < 4; ++kf) {
            uint32_t a00, a01, a02, a03, a10, a11, a12, a13;
            uint32_t b00, b01, b10, b11, b20, b21, b30, b31;
            LDSM_X4(a00, a01, a02, a03, aA0 + kf * 32);
            LDSM_X4(a10, a11, a12, a13, aA1 + kf * 32);
            LDSM_X4(b00, b01, b10, b11, bB0 + kf * 32);
            LDSM_X4(b20, b21, b30, b31, bB1 + kf * 32);
            MMA_F16(acc[0][0], a00, a01, a02, a03, b00, b01);
            MMA_F16(acc[0][1], a00, a01, a02, a03, b10, b11);
            MMA_F16(acc[0][2], a00, a01, a02, a03, b20, b21);
            MMA_F16(acc[0][3], a00, a01, a02, a03, b30, b31);
            MMA_F16(acc[1][0], a10, a11, a12, a13, b00, b01);
            MMA_F16(acc[1][1], a10, a11, a12, a13, b10, b11);
            MMA_F16(acc[1][2], a10, a11, a12, a13, b20, b21);
            MMA_F16(acc[1][3], a10, a11, a12, a13, b30, b31);
        }
        __syncthreads();
    }

#pragma unroll
    for (int mt = 0; mt < 2; ++mt) {
        int row = m0 + wr * 32 + mt * 16 + g;
#pragma unroll
        for (int nt = 0; nt < 4; ++nt) {
            int col = n0 + wc * 32 + nt * 8 + 2 * t;
            float2 bb = *(const float2*)&bias[col];
            float v00 = acc[mt][nt][0] + bb.x, v01 = acc[mt][nt][1] + bb.y;
            float v10 = acc[mt][nt][2] + bb.x, v11 = acc[mt][nt][3] + bb.y;
            if (which == 0) {
                *(__half2*)&g_Qh[(size_t)row * C_DIM + col] =
                    __floats2half2_rn(v00 * SCALE_L2E, v01 * SCALE_L2E);
                *(__half2*)&g_Qh[(size_t)(row + 8) * C_DIM + col] =
                    __floats2half2_rn(v10 * SCALE_L2E, v11 * SCALE_L2E);
            } else if (which == 1) {
                *(__half2*)&g_Kh[(size_t)row * C_DIM + col] = __floats2half2_rn(v00, v01);
                *(__half2*)&g_Kh[(size_t)(row + 8) * C_DIM + col] = __floats2half2_rn(v10, v11);
            } else {
                *(float2*)&g_Vp[(size_t)row * C_DIM + col]       = make_float2(v00, v01);
                *(float2*)&g_Vp[(size_t)(row + 8) * C_DIM + col] = make_float2(v10, v11);
            }
        }
    }
}

// ============================================================================
// V transpose + fp16: g_Vth[b][d][t] = half(g_Vp[b][t][d]). 32x32 tiles.
// ============================================================================
__global__ __launch_bounds__(256) void vtrans_kernel()
{
    __shared__ float tile[32][33];
    const int b = blockIdx.z;
    const int t0 = blockIdx.x * 32, c0 = blockIdx.y * 32;
    const float* src = g_Vp + ((size_t)b * T_DIM + t0) * C_DIM + c0;
    __half* dst      = g_Vth + ((size_t)b * C_DIM + c0) * T_DIM + t0;
    const int tx = threadIdx.x & 31, ty = threadIdx.x >> 5;
#pragma unroll
    for (int r = ty; r < 32; r += 8) tile[r][tx] = src[(size_t)r * C_DIM + tx];
    __syncthreads();
#pragma unroll
    for (int r = ty; r < 32; r += 8)
        dst[(size_t)r * T_DIM + tx] = __float2half_rn(tile[tx][r]);
}

// ============================================================================
// Flash attention, fp16 m16n8k16 + ldmatrix.x4, full-d tiles, 5 barriers/tile.
// 512 THREADS (16 warps, 4/SMSP) in a 4x4 warp grid: S = 16x16/warp,
// O = 16 rows x 4x32-col slices/warp (64 regs). Q pre-scaled by scale*log2e.
// ============================================================================
#define OFF_Q   0
#define Q_ROWB  1040
#define OFF_K   (OFF_Q + 64 * Q_ROWB)
#define K_ROWB  1040
#define OFF_V   (OFF_K + 64 * K_ROWB)
#define V_ROWB  144
#define OFF_SF  (OFF_V + 512 * V_ROWB)
#define SF_STR  68
#define PH_ROWB 144
#define PH_ROWH 72
#define OFF_ST  (OFF_SF + 64 * SF_STR * 4)
#define SMEM_BYTES (OFF_ST + 3 * 64 * 4)

__global__ __launch_bounds__(512, 1) void attn_kernel(float* __restrict__ out)
{
    extern __shared__ char sm[];
    float* Sf    = (float*)(sm + OFF_SF);
    __half* Ph   = (__half*)(sm + OFF_SF);            // alias (barrier-guarded)
    float* row_m  = (float*)(sm + OFF_ST);
    float* row_l  = row_m + 64;
    float* row_al = row_l + 64;

    const int bid = blockIdx.x;
    const int b = bid >> 6;
    const int j = bid & 63;
    const int qt = (j & 1) ? (j >> 1) : (63 - (j >> 1));  // zig-zag balance

    const __half* Qg  = g_Qh  + ((size_t)b * T_DIM + (size_t)qt * 64) * C_DIM;
    const __half* Kg  = g_Kh  + (size_t)b * T_DIM * C_DIM;
    const __half* Vtg = g_Vth + (size_t)b * C_DIM * T_DIM;

    const int tid = threadIdx.x, lane = tid & 31, wid = tid >> 5;
    const int wr = wid >> 2, wc = wid & 3;           // 4 x 4 warp grid
    const int g = lane >> 2, t = lane & 3;
    const int r0 = wr * 16 + g;

    const uint32_t smb = (uint32_t)__cvta_generic_to_shared(sm);
    const int arow = (lane & 15), akh = (lane >> 4) * 8;
    const uint32_t qA = smb + OFF_Q + (wr * 16 + arow) * Q_ROWB + akh * 2;
    const uint32_t pA = smb + OFF_SF + (wr * 16 + arow) * PH_ROWB + akh * 2;
    const int brow = ((lane >> 4) << 3) + (lane & 7), bkh = ((lane >> 3) & 1) * 8;
    const uint32_t kB = smb + OFF_K + (wc * 16 + brow) * K_ROWB + bkh * 2;
    const uint32_t vB = smb + OFF_V + (wc * 32 + brow) * V_ROWB + bkh * 2;

    auto issueK = [&](int ktile) {
#pragma unroll
        for (int r = 0; r < 8; r++) {
            int i = tid + 512 * r;
            int row = i >> 6, cf = i & 63;
            cp16(sm + OFF_K + row * K_ROWB + cf * 16,
                 Kg + (size_t)(ktile * 64 + row) * C_DIM + cf * 8);
        }
        CP_COMMIT;
    };
    auto issueV = [&](int ktile) {
#pragma unroll
        for (int r = 0; r < 8; r++) {
            int i = tid + 512 * r;
            int row = i >> 3, cf = i & 7;
            cp16(sm + OFF_V + row * V_ROWB + cf * 16,
                 Vtg + (size_t)row * T_DIM + ktile * 64 + cf * 8);
        }
        CP_COMMIT;
    };

    for (int i = tid; i < 4096; i += 512) {
        int row = i >> 6, cf = i & 63;
        cp16(sm + OFF_Q + row * Q_ROWB + cf * 16, Qg + (size_t)row * C_DIM + cf * 8);
    }
    CP_COMMIT;
    issueK(0);
    if (tid < 64) { row_m[tid] = -CUDART_INF_F; row_l[tid] = 0.f; }

    // O: warp owns rows [wr*16,+16), cols {c*128 + wc*32 + nt*8} c=0..3, nt=0..3
    float o[4][4][4];
#pragma unroll
    for (int c = 0; c < 4; c++)
#pragma unroll
        for (int n = 0; n < 4; n++)
#pragma unroll
            for (int e = 0; e < 4; e++) o[c][n][e] = 0.f;

    const int nkt = qt + 1;
    for (int kt = 0; kt < nkt; ++kt) {
        CP_WAIT(0);
        __syncthreads();
        issueV(kt);

        // ---------------- S = Q K^T (16x16 per warp) ----------------
        float sacc[2][4];
#pragma unroll
        for (int n = 0; n < 2; n++)
#pragma unroll
            for (int e = 0; e < 4; e++) sacc[n][e] = 0.f;

#pragma unroll 8
        for (int ks = 0; ks < 32; ++ks) {
            uint32_t a0, a1, a2, a3, b0, b1, b2, b3;
            LDSM_X4(a0, a1, a2, a3, qA + ks * 32);
            LDSM_X4(b0, b1, b2, b3, kB + ks * 32);
            MMA_F16(sacc[0], a0, a1, a2, a3, b0, b1);
            MMA_F16(sacc[1], a0, a1, a2, a3, b2, b3);
        }

        // ---------------- mask + store S (f32) ----------------
        const bool diag = (kt == qt);
#pragma unroll
        for (int nt = 0; nt < 2; ++nt) {
            int c0 = wc * 16 + nt * 8 + 2 * t;
            float s0 = sacc[nt][0], s1 = sacc[nt][1], s2 = sacc[nt][2], s3 = sacc[nt][3];
            if (diag) {
                if (c0     > r0)     s0 = -1e30f;
                if (c0 + 1 > r0)     s1 = -1e30f;
                if (c0     > r0 + 8) s2 = -1e30f;
                if (c0 + 1 > r0 + 8) s3 = -1e30f;
            }
            *(float2*)&Sf[r0 * SF_STR + c0]       = make_float2(s0, s1);
            *(float2*)&Sf[(r0 + 8) * SF_STR + c0] = make_float2(s2, s3);
        }
        __syncthreads();

        if (kt + 1 < nkt) issueK(kt + 1);

        // ---------------- online softmax (base-2; 8 elems/thread) ------------
        {
            int row = tid >> 3, seg = tid & 7;
            const float* pr = Sf + row * SF_STR + seg * 8;
            float vloc[8];
            float mx = -CUDART_INF_F;
#pragma unroll
            for (int i = 0; i < 8; i++) { vloc[i] = pr[i]; mx = fmaxf(mx, vloc[i]); }
            mx = fmaxf(mx, __shfl_xor_sync(0xffffffffu, mx, 1));
            mx = fmaxf(mx, __shfl_xor_sync(0xffffffffu, mx, 2));
            mx = fmaxf(mx, __shfl_xor_sync(0xffffffffu, mx, 4));
            float mold = row_m[row];
            float mnew = fmaxf(mold, mx);
            __syncthreads();            // ALL f32 reads of Sf complete
            __half* ph = Ph + row * PH_ROWH + seg * 8;
            float sum = 0.f;
#pragma unroll
            for (int i = 0; i < 8; i++) {
                __half hp = __float2half_rn(exp2f(vloc[i] - mnew));
                ph[i] = hp;
                sum += __half2float(hp);
            }
            sum += __shfl_xor_sync(0xffffffffu, sum, 1);
            sum += __shfl_xor_sync(0xffffffffu, sum, 2);
            sum += __shfl_xor_sync(0xffffffffu, sum, 4);
            if (seg == 0) {
                float alpha = exp2f(mold - mnew);
                row_al[row] = alpha;
                row_l[row] = row_l[row] * alpha + sum;
                row_m[row] = mnew;
            }
        }
        __syncthreads();

        // ---------------- rescale O, cache P fragments ----------------
        {
            float al0 = row_al[r0], al1 = row_al[r0 + 8];
#pragma unroll
            for (int c = 0; c < 4; c++)
#pragma unroll
                for (int nt = 0; nt < 4; nt++) {
                    o[c][nt][0] *= al0; o[c][nt][1] *= al0;
                    o[c][nt][2] *= al1; o[c][nt][3] *= al1;
                }
        }
        uint32_t pa[4][4];
#pragma unroll
        for (int ks = 0; ks < 4; ks++)
            LDSM_X4(pa[ks][0], pa[ks][1], pa[ks][2], pa[ks][3], pA + ks * 32);

        if (kt + 1 < nkt) { CP_WAIT(1); } else { CP_WAIT(0); }
        __syncthreads();

        // ---------------- O += P V ----------------
#pragma unroll
        for (int ks = 0; ks < 4; ++ks) {
#pragma unroll
            for (int c = 0; c < 4; ++c) {
#pragma unroll
                for (int vr = 0; vr < 2; ++vr) {
                    uint32_t v0, v1, v2, v3;
                    LDSM_X4(v0, v1, v2, v3,
                            vB + (uint32_t)(c * 128 + vr * 16) * V_ROWB + ks * 32);
                    MMA_F16(o[c][vr * 2],     pa[ks][0], pa[ks][1], pa[ks][2], pa[ks][3], v0, v1);
                    MMA_F16(o[c][vr * 2 + 1], pa[ks][0], pa[ks][1], pa[ks][2], pa[ks][3], v2, v3);
                }
            }
        }
    }

    // ---------------- epilogue ----------------
    {
        float inv0 = 1.f / row_l[r0];
        float inv1 = 1.f / row_l[r0 + 8];
        float* og = out + ((size_t)b * T_DIM + (size_t)qt * 64) * C_DIM;
#pragma unroll
        for (int c = 0; c < 4; c++) {
#pragma unroll
            for (int nt = 0; nt < 4; nt++) {
                int col = c * 128 + wc * 32 + nt * 8 + 2 * t;
                *(float2*)&og[(size_t)r0 * C_DIM + col] =
                    make_float2(o[c][nt][0] * inv0, o[c][nt][1] * inv0);
                *(float2*)&og[(size_t)(r0 + 8) * C_DIM + col] =
                    make_float2(o[c][nt][2] * inv1, o[c][nt][3] * inv1);
            }
        }
    }
}

// ============================================================================
// Launch
// ============================================================================
extern "C" void kernel_launch(void* const* d_in, const int* in_sizes, int n_in,
                              void* d_out, int out_size)
{
    const float* q  = (const float*)d_in[0];
    const float* k  = (const float*)d_in[1];
    const float* v  = (const float*)d_in[2];
    const float* Wq = (const float*)d_in[3];
    const float* bq = (const float*)d_in[4];
    const float* Wk = (const float*)d_in[5];
    const float* bk = (const float*)d_in[6];
    const float* Wv = (const float*)d_in[7];
    const float* bv = (const float*)d_in[8];
    float* out = (float*)d_out;

    cudaFuncSetAttribute(proj_kernel, cudaFuncAttributeMaxDynamicSharedMemorySize, PJ_SMEM);
    cudaFuncSetAttribute(attn_kernel, cudaFuncAttributeMaxDynamicSharedMemorySize, SMEM_BYTES);

    dim3 cgrid(NEL / (256 * 8), 1, 3);
    xconv_kernel<<<cgrid, 256>>>(q, k, v);

    dim3 wgrid(C_DIM / 32, C_DIM / 32, 3);
    wtrans_kernel<<<wgrid, 256>>>(Wq, Wk, Wv);

    dim3 pgrid(16384 / 128, 512 / 64, 3);
    proj_kernel<<<pgrid, 256, PJ_SMEM>>>(bq, bk, bv);

    dim3 tgrid(T_DIM / 32, C_DIM / 32, B_DIM);
    vtrans_kernel<<<tgrid, 256>>>();

    attn_kernel<<<B_DIM * (T_DIM / 64), 512, SMEM_BYTES>>>(out);
}

// round 16
// speedup vs baseline: 1.1020x; 1.1020x over previous
#include <cuda_runtime.h>
#include <cuda_fp16.h>
#include <cstdint>
#include <math_constants.h>

#define B_DIM 4
#define T_DIM 4096
#define C_DIM 512
#define NEL   (B_DIM * T_DIM * C_DIM)
// scale * log2(e): Q is pre-multiplied so softmax uses exp2 directly
#define SCALE_L2E (0.044194173824159216f * 1.4426950408889634f)

// Scratch
__device__ __half g_Xh [3 * NEL];                 // fp16 inputs (q,k,v)
__device__ __half g_Wth[3 * C_DIM * C_DIM];       // fp16 W^T [n][k]
__device__ __half g_Qh [NEL];                     // Q proj * scale*log2e
__device__ __half g_Kh [NEL];
__device__ float  g_Vp [NEL];                     // V proj fp32
__device__ __half g_Vth[NEL];                     // V transposed [b][d][t]

__device__ __forceinline__ void cp16(void* s, const void* g) {
    uint32_t sa = (uint32_t)__cvta_generic_to_shared(s);
    asm volatile("cp.async.cg.shared.global [%0], [%1], 16;" :: "r"(sa), "l"(g));
}
#define CP_COMMIT asm volatile("cp.async.commit_group;")
#define CP_WAIT(N) asm volatile("cp.async.wait_group %0;" :: "n"(N))

#define MMA_F16(d, a0, a1, a2, a3, b0, b1)                                   \
    asm volatile(                                                            \
        "mma.sync.aligned.m16n8k16.row.col.f32.f16.f16.f32 "                 \
        "{%0,%1,%2,%3},{%4,%5,%6,%7},{%8,%9},{%0,%1,%2,%3};"                 \
        : "+f"((d)[0]), "+f"((d)[1]), "+f"((d)[2]), "+f"((d)[3])             \
        : "r"(a0), "r"(a1), "r"(a2), "r"(a3), "r"(b0), "r"(b1))

#define LDSM_X4(r0, r1, r2, r3, addr)                                        \
    asm volatile("ldmatrix.sync.aligned.m8n8.x4.shared.b16 {%0,%1,%2,%3}, [%4];" \
        : "=r"(r0), "=r"(r1), "=r"(r2), "=r"(r3) : "r"(addr))

// ============================================================================
// xconv: fp32 -> fp16 elementwise, 3 tensors. 8 floats/thread.
// ============================================================================
__global__ __launch_bounds__(256) void xconv_kernel(
    const float* __restrict__ xq, const float* __restrict__ xk, const float* __restrict__ xv)
{
    const int which = blockIdx.z;
    const float* src = (which == 0) ? xq : (which == 1) ? xk : xv;
    __half* dst = g_Xh + (size_t)which * NEL;
    size_t i = ((size_t)blockIdx.x * 256 + threadIdx.x) * 8;
    float4 f0 = *(const float4*)(src + i);
    float4 f1 = *(const float4*)(src + i + 4);
    __half2 h0 = __floats2half2_rn(f0.x, f0.y);
    __half2 h1 = __floats2half2_rn(f0.z, f0.w);
    __half2 h2 = __floats2half2_rn(f1.x, f1.y);
    __half2 h3 = __floats2half2_rn(f1.z, f1.w);
    uint4 u;
    u.x = *(uint32_t*)&h0; u.y = *(uint32_t*)&h1;
    u.z = *(uint32_t*)&h2; u.w = *(uint32_t*)&h3;
    *(uint4*)(dst + i) = u;
}

// ============================================================================
// wtrans: W [k][n] fp32 -> W^T [n][k] fp16. 32x32 tiles.
// ============================================================================
__global__ __launch_bounds__(256) void wtrans_kernel(
    const float* __restrict__ Wq, const float* __restrict__ Wk, const float* __restrict__ Wv)
{
    __shared__ float tile[32][33];
    const int which = blockIdx.z;
    const float* W = (which == 0) ? Wq : (which == 1) ? Wk : Wv;
    __half* Wt = g_Wth + (size_t)which * C_DIM * C_DIM;
    const int k0 = blockIdx.x * 32, n0 = blockIdx.y * 32;
    const int tx = threadIdx.x & 31, ty = threadIdx.x >> 5;
#pragma unroll
    for (int r = ty; r < 32; r += 8) tile[r][tx] = W[(size_t)(k0 + r) * C_DIM + n0 + tx];
    __syncthreads();
#pragma unroll
    for (int r = ty; r < 32; r += 8)
        Wt[(size_t)(n0 + r) * C_DIM + k0 + tx] = __float2half_rn(tile[tx][r]);
}

// ============================================================================
// proj: y = x @ W + b via fp16 m16n8k16 + ldmatrix. BM=128, BN=64, BK=64.
// 256 threads (4m x 2n warps). which 0: g_Qh (*scale*log2e); 1: g_Kh; 2: g_Vp f32.
// ============================================================================
#define PJ_A(buf)  ((buf) * 18432)            // 128 rows x 144B
#define PJ_B(buf)  (36864 + (buf) * 9216)     // 64 rows x 144B
#define PJ_SMEM    55296
#define PJ_ROWB    144

__global__ __launch_bounds__(256, 1) void proj_kernel(
    const float* __restrict__ bq, const float* __restrict__ bk, const float* __restrict__ bv)
{
    extern __shared__ char sm[];
    const int which = blockIdx.z;
    const __half* xh = g_Xh + (size_t)which * NEL;
    const __half* wt = g_Wth + (size_t)which * C_DIM * C_DIM;
    const float* bias = (which == 0) ? bq : (which == 1) ? bk : bv;

    const int m0 = blockIdx.x * 128;
    const int n0 = blockIdx.y * 64;
    const int tid = threadIdx.x, lane = tid & 31, wid = tid >> 5;
    const int wr = wid >> 1, wc = wid & 1;
    const int g = lane >> 2, t = lane & 3;

    const uint32_t smb = (uint32_t)__cvta_generic_to_shared(sm);
    const int arow = (lane & 15), akh = (lane >> 4) * 8;
    const int brow = ((lane >> 4) << 3) + (lane & 7), bkh = ((lane >> 3) & 1) * 8;

    float acc[2][4][4];
#pragma unroll
    for (int mt = 0; mt < 2; mt++)
#pragma unroll
        for (int nt = 0; nt < 4; nt++)
#pragma unroll
            for (int e = 0; e < 4; e++) acc[mt][nt][e] = 0.f;

    auto issue = [&](int buf, int kt) {
#pragma unroll
        for (int r = 0; r < 4; r++) {             // A: 128 x 64 halves
            int i = tid + 256 * r;
            int row = i >> 3, cf = i & 7;
            cp16(sm + PJ_A(buf) + row * PJ_ROWB + cf * 16,
                 xh + (size_t)(m0 + row) * C_DIM + kt * 64 + cf * 8);
        }
#pragma unroll
        for (int r = 0; r < 2; r++) {             // B: 64 x 64 halves
            int i = tid + 256 * r;
            int row = i >> 3, cf = i & 7;
            cp16(sm + PJ_B(buf) + row * PJ_ROWB + cf * 16,
                 wt + (size_t)(n0 + row) * C_DIM + kt * 64 + cf * 8);
        }
        CP_COMMIT;
    };

    issue(0, 0);
    for (int kt = 0; kt < 8; ++kt) {
        if (kt + 1 < 8) { issue((kt + 1) & 1, kt + 1); CP_WAIT(1); }
        else            { CP_WAIT(0); }
        __syncthreads();
        const int buf = kt & 1;
        const uint32_t aA0 = smb + PJ_A(buf) + (wr * 32 + arow) * PJ_ROWB + akh * 2;
        const uint32_t aA1 = aA0 + 16 * PJ_ROWB;
        const uint32_t bB0 = smb + PJ_B(buf) + (wc * 32 + brow) * PJ_ROWB + bkh * 2;
        const uint32_t bB1 = bB0 + 16 * PJ_ROWB;
#pragma unroll
        for (int kf = 0; kf < 4; ++kf) {
            uint32_t a00, a01, a02, a03, a10, a11, a12, a13;
            uint32_t b00, b01, b10, b11, b20, b21, b30, b31;
            LDSM_X4(a00, a01, a02, a03, aA0 + kf * 32);
            LDSM_X4(a10, a11, a12, a13, aA1 + kf * 32);
            LDSM_X4(b00, b01, b10, b11, bB0 + kf * 32);
            LDSM_X4(b20, b21, b30, b31, bB1 + kf * 32);
            MMA_F16(acc[0][0], a00, a01, a02, a03, b00, b01);
            MMA_F16(acc[0][1], a00, a01, a02, a03, b10, b11);
            MMA_F16(acc[0][2], a00, a01, a02, a03, b20, b21);
            MMA_F16(acc[0][3], a00, a01, a02, a03, b30, b31);
            MMA_F16(acc[1][0], a10, a11, a12, a13, b00, b01);
            MMA_F16(acc[1][1], a10, a11, a12, a13, b10, b11);
            MMA_F16(acc[1][2], a10, a11, a12, a13, b20, b21);
            MMA_F16(acc[1][3], a10, a11, a12, a13, b30, b31);
        }
        __syncthreads();
    }

#pragma unroll
    for (int mt = 0; mt < 2; ++mt) {
        int row = m0 + wr * 32 + mt * 16 + g;
#pragma unroll
        for (int nt = 0; nt < 4; ++nt) {
            int col = n0 + wc * 32 + nt * 8 + 2 * t;
            float2 bb = *(const float2*)&bias[col];
            float v00 = acc[mt][nt][0] + bb.x, v01 = acc[mt][nt][1] + bb.y;
            float v10 = acc[mt][nt][2] + bb.x, v11 = acc[mt][nt][3] + bb.y;
            if (which == 0) {
                *(__half2*)&g_Qh[(size_t)row * C_DIM + col] =
                    __floats2half2_rn(v00 * SCALE_L2E, v01 * SCALE_L2E);
                *(__half2*)&g_Qh[(size_t)(row + 8) * C_DIM + col] =
                    __floats2half2_rn(v10 * SCALE_L2E, v11 * SCALE_L2E);
            } else if (which == 1) {
                *(__half2*)&g_Kh[(size_t)row * C_DIM + col] = __floats2half2_rn(v00, v01);
                *(__half2*)&g_Kh[(size_t)(row + 8) * C_DIM + col] = __floats2half2_rn(v10, v11);
            } else {
                *(float2*)&g_Vp[(size_t)row * C_DIM + col]       = make_float2(v00, v01);
                *(float2*)&g_Vp[(size_t)(row + 8) * C_DIM + col] = make_float2(v10, v11);
            }
        }
    }
}

// ============================================================================
// V transpose + fp16: g_Vth[b][d][t] = half(g_Vp[b][t][d]). 32x32 tiles.
// ============================================================================
__global__ __launch_bounds__(256) void vtrans_kernel()
{
    __shared__ float tile[32][33];
    const int b = blockIdx.z;
    const int t0 = blockIdx.x * 32, c0 = blockIdx.y * 32;
    const float* src = g_Vp + ((size_t)b * T_DIM + t0) * C_DIM + c0;
    __half* dst      = g_Vth + ((size_t)b * C_DIM + c0) * T_DIM + t0;
    const int tx = threadIdx.x & 31, ty = threadIdx.x >> 5;
#pragma unroll
    for (int r = ty; r < 32; r += 8) tile[r][tx] = src[(size_t)r * C_DIM + tx];
    __syncthreads();
#pragma unroll
    for (int r = ty; r < 32; r += 8)
        dst[(size_t)r * T_DIM + tx] = __float2half_rn(tile[tx][r]);
}

// ============================================================================
// Flash attention (round-12 champion base, 256 threads). S phase: 4x2 warp
// grid (unchanged). PV phase RE-MAPPED to 2(row)x4(d) warp grid: each warp
// owns 32 rows x 128 d-cols, halving V smem re-reads (256KB -> 128KB/tile).
// Q pre-scaled by scale*log2e; softmax = bare exp2f.
// ============================================================================
#define OFF_Q   0
#define Q_ROWB  1040
#define OFF_K   (OFF_Q + 64 * Q_ROWB)
#define K_ROWB  1040
#define OFF_V   (OFF_K + 64 * K_ROWB)
#define V_ROWB  144
#define OFF_SF  (OFF_V + 512 * V_ROWB)
#define SF_STR  68
#define PH_ROWB 144
#define PH_ROWH 72
#define OFF_ST  (OFF_SF + 64 * SF_STR * 4)
#define SMEM_BYTES (OFF_ST + 3 * 64 * 4)

__global__ __launch_bounds__(256, 1) void attn_kernel(float* __restrict__ out)
{
    extern __shared__ char sm[];
    float* Sf    = (float*)(sm + OFF_SF);
    __half* Ph   = (__half*)(sm + OFF_SF);            // alias (barrier-guarded)
    float* row_m  = (float*)(sm + OFF_ST);
    float* row_l  = row_m + 64;
    float* row_al = row_l + 64;

    const int bid = blockIdx.x;
    const int b = bid >> 6;
    const int j = bid & 63;
    const int qt = (j & 1) ? (j >> 1) : (63 - (j >> 1));  // zig-zag balance

    const __half* Qg  = g_Qh  + ((size_t)b * T_DIM + (size_t)qt * 64) * C_DIM;
    const __half* Kg  = g_Kh  + (size_t)b * T_DIM * C_DIM;
    const __half* Vtg = g_Vth + (size_t)b * C_DIM * T_DIM;

    const int tid = threadIdx.x, lane = tid & 31, wid = tid >> 5;
    const int wr = wid >> 1, wc = wid & 1;            // S phase: 4x2
    const int wr2 = wid >> 2, wc4 = wid & 3;          // PV phase: 2x4
    const int g = lane >> 2, t = lane & 3;
    const int r0 = wr * 16 + g;                       // S-phase row
    const int p0 = wr2 * 32 + g;                      // PV-phase row base

    const uint32_t smb = (uint32_t)__cvta_generic_to_shared(sm);
    const int arow = (lane & 15), akh = (lane >> 4) * 8;
    const uint32_t qA  = smb + OFF_Q + (wr * 16 + arow) * Q_ROWB + akh * 2;
    const uint32_t pA0 = smb + OFF_SF + (wr2 * 32 + arow) * PH_ROWB + akh * 2;
    const uint32_t pA1 = pA0 + 16 * PH_ROWB;
    const int brow = ((lane >> 4) << 3) + (lane & 7), bkh = ((lane >> 3) & 1) * 8;
    const uint32_t kB0 = smb + OFF_K + (wc * 32 + brow) * K_ROWB + bkh * 2;
    const uint32_t kB1 = kB0 + 16 * K_ROWB;
    const uint32_t vB  = smb + OFF_V + (wc4 * 128 + brow) * V_ROWB + bkh * 2;

    auto issueK = [&](int ktile) {
#pragma unroll
        for (int r = 0; r < 16; r++) {
            int i = tid + 256 * r;
            int row = i >> 6, cf = i & 63;
            cp16(sm + OFF_K + row * K_ROWB + cf * 16,
                 Kg + (size_t)(ktile * 64 + row) * C_DIM + cf * 8);
        }
        CP_COMMIT;
    };
    auto issueV = [&](int ktile) {
#pragma unroll
        for (int r = 0; r < 16; r++) {
            int i = tid + 256 * r;
            int row = i >> 3, cf = i & 7;
            cp16(sm + OFF_V + row * V_ROWB + cf * 16,
                 Vtg + (size_t)row * T_DIM + ktile * 64 + cf * 8);
        }
        CP_COMMIT;
    };

    for (int i = tid; i < 4096; i += 256) {
        int row = i >> 6, cf = i & 63;
        cp16(sm + OFF_Q + row * Q_ROWB + cf * 16, Qg + (size_t)row * C_DIM + cf * 8);
    }
    CP_COMMIT;
    issueK(0);
    if (tid < 64) { row_m[tid] = -CUDART_INF_F; row_l[tid] = 0.f; }

    // O (PV 2x4 map): warp owns rows [wr2*32,+32) as 2 m16 groups, d-cols
    // [wc4*128,+128) as 16 n8 blocks: o[m][nb][4].
    float o[2][16][4];
#pragma unroll
    for (int m = 0; m < 2; m++)
#pragma unroll
        for (int n = 0; n < 16; n++)
#pragma unroll
            for (int e = 0; e < 4; e++) o[m][n][e] = 0.f;

    const int nkt = qt + 1;
    for (int kt = 0; kt < nkt; ++kt) {
        CP_WAIT(0);
        __syncthreads();
        issueV(kt);

        // ---------------- S = Q K^T (4x2 map, unchanged) ----------------
        float sacc[4][4];
#pragma unroll
        for (int n = 0; n < 4; n++)
#pragma unroll
            for (int e = 0; e < 4; e++) sacc[n][e] = 0.f;

#pragma unroll 8
        for (int ks = 0; ks < 32; ++ks) {
            uint32_t a0, a1, a2, a3, b00, b01, b10, b11, b20, b21, b30, b31;
            LDSM_X4(a0, a1, a2, a3, qA + ks * 32);
            LDSM_X4(b00, b01, b10, b11, kB0 + ks * 32);
            LDSM_X4(b20, b21, b30, b31, kB1 + ks * 32);
            MMA_F16(sacc[0], a0, a1, a2, a3, b00, b01);
            MMA_F16(sacc[1], a0, a1, a2, a3, b10, b11);
            MMA_F16(sacc[2], a0, a1, a2, a3, b20, b21);
            MMA_F16(sacc[3], a0, a1, a2, a3, b30, b31);
        }

        // ---------------- mask + store S (f32) ----------------
        const bool diag = (kt == qt);
#pragma unroll
        for (int nt = 0; nt < 4; ++nt) {
            int c0 = wc * 32 + nt * 8 + 2 * t;
            float s0 = sacc[nt][0], s1 = sacc[nt][1], s2 = sacc[nt][2], s3 = sacc[nt][3];
            if (diag) {
                if (c0     > r0)     s0 = -1e30f;
                if (c0 + 1 > r0)     s1 = -1e30f;
                if (c0     > r0 + 8) s2 = -1e30f;
                if (c0 + 1 > r0 + 8) s3 = -1e30f;
            }
            *(float2*)&Sf[r0 * SF_STR + c0]       = make_float2(s0, s1);
            *(float2*)&Sf[(r0 + 8) * SF_STR + c0] = make_float2(s2, s3);
        }
        __syncthreads();

        if (kt + 1 < nkt) issueK(kt + 1);

        // ---------------- online softmax (base-2; Q pre-scaled) -------------
        {
            int row = tid >> 2, seg = tid & 3;
            const float* pr = Sf + row * SF_STR + seg * 16;
            float vloc[16];
            float mx = -CUDART_INF_F;
#pragma unroll
            for (int i = 0; i < 16; i++) { vloc[i] = pr[i]; mx = fmaxf(mx, vloc[i]); }
            mx = fmaxf(mx, __shfl_xor_sync(0xffffffffu, mx, 1));
            mx = fmaxf(mx, __shfl_xor_sync(0xffffffffu, mx, 2));
            float mold = row_m[row];
            float mnew = fmaxf(mold, mx);
            __syncthreads();            // ALL f32 reads of Sf complete
            __half* ph = Ph + row * PH_ROWH + seg * 16;
            float sum = 0.f;
#pragma unroll
            for (int i = 0; i < 16; i++) {
                __half hp = __float2half_rn(exp2f(vloc[i] - mnew));
                ph[i] = hp;
                sum += __half2float(hp);
            }
            sum += __shfl_xor_sync(0xffffffffu, sum, 1);
            sum += __shfl_xor_sync(0xffffffffu, sum, 2);
            if (seg == 0) {
                float alpha = exp2f(mold - mnew);
                row_al[row] = alpha;
                row_l[row] = row_l[row] * alpha + sum;
                row_m[row] = mnew;
            }
        }
        __syncthreads();

        // ---------------- rescale O (PV rows), cache P fragments ------------
        {
            float al00 = row_al[p0],      al01 = row_al[p0 + 8];
            float al10 = row_al[p0 + 16], al11 = row_al[p0 + 24];
#pragma unroll
            for (int n = 0; n < 16; n++) {
                o[0][n][0] *= al00; o[0][n][1] *= al00;
                o[0][n][2] *= al01; o[0][n][3] *= al01;
                o[1][n][0] *= al10; o[1][n][1] *= al10;
                o[1][n][2] *= al11; o[1][n][3] *= al11;
            }
        }
        uint32_t pa[2][4][4];
#pragma unroll
        for (int ks = 0; ks < 4; ks++) {
            LDSM_X4(pa[0][ks][0], pa[0][ks][1], pa[0][ks][2], pa[0][ks][3], pA0 + ks * 32);
            LDSM_X4(pa[1][ks][0], pa[1][ks][1], pa[1][ks][2], pa[1][ks][3], pA1 + ks * 32);
        }

        if (kt + 1 < nkt) { CP_WAIT(1); } else { CP_WAIT(0); }
        __syncthreads();

        // ---------------- O += P V (2x4 map: 32 LDSM + 128 MMA/warp) --------
#pragma unroll
        for (int ks = 0; ks < 4; ++ks) {
#pragma unroll
            for (int vr = 0; vr < 8; ++vr) {
                uint32_t v0, v1, v2, v3;
                LDSM_X4(v0, v1, v2, v3, vB + (uint32_t)(vr * 16) * V_ROWB + ks * 32);
                MMA_F16(o[0][vr * 2],     pa[0][ks][0], pa[0][ks][1], pa[0][ks][2], pa[0][ks][3], v0, v1);
                MMA_F16(o[0][vr * 2 + 1], pa[0][ks][0], pa[0][ks][1], pa[0][ks][2], pa[0][ks][3], v2, v3);
                MMA_F16(o[1][vr * 2],     pa[1][ks][0], pa[1][ks][1], pa[1][ks][2], pa[1][ks][3], v0, v1);
                MMA_F16(o[1][vr * 2 + 1], pa[1][ks][0], pa[1][ks][1], pa[1][ks][2], pa[1][ks][3], v2, v3);
            }
        }
    }

    // ---------------- epilogue (PV 2x4 map) ----------------
    {
        float* og = out + ((size_t)b * T_DIM + (size_t)qt * 64) * C_DIM;
#pragma unroll
        for (int m = 0; m < 2; m++) {
            int rowa = p0 + m * 16;
            float inv0 = 1.f / row_l[rowa];
            float inv1 = 1.f / row_l[rowa + 8];
#pragma unroll
            for (int nb = 0; nb < 16; nb++) {
                int col = wc4 * 128 + nb * 8 + 2 * t;
                *(float2*)&og[(size_t)rowa * C_DIM + col] =
                    make_float2(o[m][nb][0] * inv0, o[m][nb][1] * inv0);
                *(float2*)&og[(size_t)(rowa + 8) * C_DIM + col] =
                    make_float2(o[m][nb][2] * inv1, o[m][nb][3] * inv1);
            }
        }
    }
}

// ============================================================================
// Launch
// ============================================================================
extern "C" void kernel_launch(void* const* d_in, const int* in_sizes, int n_in,
                              void* d_out, int out_size)
{
    const float* q  = (const float*)d_in[0];
    const float* k  = (const float*)d_in[1];
    const float* v  = (const float*)d_in[2];
    const float* Wq = (const float*)d_in[3];
    const float* bq = (const float*)d_in[4];
    const float* Wk = (const float*)d_in[5];
    const float* bk = (const float*)d_in[6];
    const float* Wv = (const float*)d_in[7];
    const float* bv = (const float*)d_in[8];
    float* out = (float*)d_out;

    cudaFuncSetAttribute(proj_kernel, cudaFuncAttributeMaxDynamicSharedMemorySize, PJ_SMEM);
    cudaFuncSetAttribute(attn_kernel, cudaFuncAttributeMaxDynamicSharedMemorySize, SMEM_BYTES);

    dim3 cgrid(NEL / (256 * 8), 1, 3);
    xconv_kernel<<<cgrid, 256>>>(q, k, v);

    dim3 wgrid(C_DIM / 32, C_DIM / 32, 3);
    wtrans_kernel<<<wgrid, 256>>>(Wq, Wk, Wv);

    dim3 pgrid(16384 / 128, 512 / 64, 3);
    proj_kernel<<<pgrid, 256, PJ_SMEM>>>(bq, bk, bv);

    dim3 tgrid(T_DIM / 32, C_DIM / 32, B_DIM);
    vtrans_kernel<<<tgrid, 256>>>();

    attn_kernel<<<B_DIM * (T_DIM / 64), 256, SMEM_BYTES>>>(out);
}